// round 8
// baseline (speedup 1.0000x reference)
#include <cuda_runtime.h>
#include <math.h>
#include <stdint.h>

// Problem shape (fixed by the reference)
#define B 32
#define S 4096
#define H 768            // 768 floats = 6 float4 per lane across a warp
#define CHUNKS 32        // CTAs per batch
#define WARPS 8          // warps per CTA
#define ROWS_PER_WARP (S / CHUNKS / WARPS)   // 16
#define NPART (B * CHUNKS)                   // 1024 CTA-level partials
#define STAGES 2

// Scratch for CTA partials + per-batch arrival counters (allocation-free).
__device__ float g_pm[NPART];
__device__ float g_pl[NPART];
__device__ float g_pacc[(size_t)NPART * H];   // 3.1 MB
__device__ unsigned int g_count[B] = {};      // reset by last CTA per replay

#define CP_ASYNC16(dst_u32, src_ptr) \
    asm volatile("cp.async.cg.shared.global [%0], [%1], 16;" \
                 :: "r"(dst_u32), "l"(src_ptr))
#define CP_COMMIT() asm volatile("cp.async.commit_group;")
#define CP_WAIT(n)  asm volatile("cp.async.wait_group %0;" :: "n"(n))

// ---------------------------------------------------------------------------
// Fused single-query attention: per-warp cp.async double-buffered row stream,
// online softmax + weighted accumulate, CTA smem merge, last-CTA combine.
// Each lane copies exactly the float4 slots it later reads (i*32+lane), so
// the per-warp pipeline needs no intra-warp synchronization.
// ---------------------------------------------------------------------------
__global__ __launch_bounds__(256, 3)
void attn_fused(const float* __restrict__ hidden, const float* __restrict__ q,
                float* __restrict__ out)
{
    const int bx    = blockIdx.x;            // 0..1023
    const int b     = bx / CHUNKS;           // batch
    const int chunk = bx % CHUNKS;
    const int wid   = threadIdx.x >> 5;
    const int lane  = threadIdx.x & 31;

    // stage buffers: [STAGES][WARPS][192 float4] = 48 KB; later aliased as
    // the 8x768 merge buffer (all async groups drained before reuse)
    __shared__ float4 s_buf[STAGES * WARPS * 192];
    __shared__ float s_m[WARPS];
    __shared__ float s_l[WARPS];
    __shared__ unsigned int s_ticket;

    const float4* qv4 = (const float4*)q;
    float4 qv[6];
#pragma unroll
    for (int i = 0; i < 6; i++) qv[i] = qv4[i * 32 + lane];

    const float* base = hidden + (size_t)b * S * H;
    const int row0 = chunk * (S / CHUNKS) + wid * ROWS_PER_WARP;

    const unsigned sb0 = (unsigned)__cvta_generic_to_shared(s_buf)
                       + (unsigned)((wid * 192 + lane) * 16);
    const unsigned sb1 = sb0 + (unsigned)(WARPS * 192 * 16);

    // issue one row into a stage (6 x 16B per lane), one commit group per row
    #define ISSUE_ROW(r, sb) do {                                        \
        const float* gp_ = base + (size_t)(row0 + (r)) * H + lane * 4;   \
        _Pragma("unroll")                                                \
        for (int i_ = 0; i_ < 6; i_++)                                   \
            CP_ASYNC16((sb) + i_ * 512, gp_ + i_ * 128);                 \
        CP_COMMIT();                                                     \
    } while (0)

    float4 acc[6];
#pragma unroll
    for (int i = 0; i < 6; i++) acc[i] = make_float4(0.f, 0.f, 0.f, 0.f);
    float m = -INFINITY;
    float l = 0.f;

    // consume the row sitting in stage buffer sp_
    #define CONSUME_ROW(sbgen) do {                                      \
        const float4* sp_ = (sbgen);                                     \
        float4 x_[6];                                                    \
        _Pragma("unroll")                                                \
        for (int i_ = 0; i_ < 6; i_++) x_[i_] = sp_[i_ * 32 + lane];     \
        float d_ = 0.f;                                                  \
        _Pragma("unroll")                                                \
        for (int i_ = 0; i_ < 6; i_++) {                                 \
            d_ = fmaf(x_[i_].x, qv[i_].x, d_);                           \
            d_ = fmaf(x_[i_].y, qv[i_].y, d_);                           \
            d_ = fmaf(x_[i_].z, qv[i_].z, d_);                           \
            d_ = fmaf(x_[i_].w, qv[i_].w, d_);                           \
        }                                                                \
        _Pragma("unroll")                                                \
        for (int o_ = 16; o_ > 0; o_ >>= 1)                              \
            d_ += __shfl_xor_sync(0xffffffffu, d_, o_);                  \
        if (d_ > m) {                                                    \
            const float sc_ = __expf(m - d_);                            \
            l *= sc_;                                                    \
            _Pragma("unroll")                                            \
            for (int i_ = 0; i_ < 6; i_++) {                             \
                acc[i_].x *= sc_; acc[i_].y *= sc_;                      \
                acc[i_].z *= sc_; acc[i_].w *= sc_;                      \
            }                                                            \
            m = d_;                                                      \
        }                                                                \
        const float w_ = __expf(d_ - m);                                 \
        l += w_;                                                         \
        _Pragma("unroll")                                                \
        for (int i_ = 0; i_ < 6; i_++) {                                 \
            acc[i_].x = fmaf(w_, x_[i_].x, acc[i_].x);                   \
            acc[i_].y = fmaf(w_, x_[i_].y, acc[i_].y);                   \
            acc[i_].z = fmaf(w_, x_[i_].z, acc[i_].z);                   \
            acc[i_].w = fmaf(w_, x_[i_].w, acc[i_].w);                   \
        }                                                                \
    } while (0)

    const float4* sp0 = s_buf + (wid * 192);
    const float4* sp1 = s_buf + (WARPS * 192 + wid * 192);

    // prologue: fill both stages
    ISSUE_ROW(0, sb0);
    ISSUE_ROW(1, sb1);

    // steady state: rows 0..13 (each issues row r+2 into the freed stage)
#pragma unroll 2
    for (int r = 0; r < ROWS_PER_WARP - 2; r += 2) {
        CP_WAIT(1);
        CONSUME_ROW(sp0);
        ISSUE_ROW(r + 2, sb0);
        CP_WAIT(1);
        CONSUME_ROW(sp1);
        if (r + 3 < ROWS_PER_WARP) ISSUE_ROW(r + 3, sb1);
    }
    // epilogue: rows 14, 15
    CP_WAIT(1);
    CONSUME_ROW(sp0);
    CP_WAIT(0);
    CONSUME_ROW(sp1);

    // ---- CTA-level merge of the 8 warp partials (alias stage memory) ----
    __syncthreads();                        // everyone done streaming
    float* s_acc = (float*)s_buf;           // [WARPS][H] = 24 KB

    if (lane == 0) { s_m[wid] = m; s_l[wid] = l; }
    {
        float4* sa = (float4*)(s_acc + wid * H);
#pragma unroll
        for (int i = 0; i < 6; i++) sa[i * 32 + lane] = acc[i];
    }
    __syncthreads();

    float M = s_m[0];
#pragma unroll
    for (int w = 1; w < WARPS; w++) M = fmaxf(M, s_m[w]);

    float* pa = g_pacc + (size_t)bx * H;
#pragma unroll
    for (int j = 0; j < 3; j++) {
        const int h = threadIdx.x + j * 256;
        float r = 0.f;
#pragma unroll
        for (int w = 0; w < WARPS; w++)
            r = fmaf(__expf(s_m[w] - M), s_acc[w * H + h], r);
        pa[h] = r;
    }
    if (threadIdx.x == 0) {
        float L = 0.f;
#pragma unroll
        for (int w = 0; w < WARPS; w++) L = fmaf(__expf(s_m[w] - M), s_l[w], L);
        g_pm[bx] = M;
        g_pl[bx] = L;
    }

    // ---- last CTA of this batch combines the 32 partials ----
    if (threadIdx.x == 0) {
        __threadfence();                    // partials visible before count
        s_ticket = atomicAdd(&g_count[b], 1u);
    }
    __syncthreads();
    if (s_ticket != CHUNKS - 1) return;

    __threadfence();                        // acquire: see all partials

    const int p0 = b * CHUNKS;
    float GM = -INFINITY;
#pragma unroll
    for (int c = 0; c < CHUNKS; c++) GM = fmaxf(GM, g_pm[p0 + c]);

    float r0 = 0.f, r1 = 0.f, r2 = 0.f, L = 0.f;
    const int h0 = threadIdx.x;
#pragma unroll 4
    for (int c = 0; c < CHUNKS; c++) {
        const float w = __expf(g_pm[p0 + c] - GM);
        const float* pc = g_pacc + (size_t)(p0 + c) * H;
        L  = fmaf(w, g_pl[p0 + c], L);
        r0 = fmaf(w, pc[h0],       r0);
        r1 = fmaf(w, pc[h0 + 256], r1);
        r2 = fmaf(w, pc[h0 + 512], r2);
    }
    const float invL = 1.f / L;
    float* ob = out + b * H;
    ob[h0]       = r0 * invL;
    ob[h0 + 256] = r1 * invL;
    ob[h0 + 512] = r2 * invL;

    if (threadIdx.x == 0) g_count[b] = 0;   // reset for next graph replay
}

extern "C" void kernel_launch(void* const* d_in, const int* in_sizes, int n_in,
                              void* d_out, int out_size)
{
    const float* hidden = (const float*)d_in[0];   // [32, 4096, 768] f32
    const float* querys = (const float*)d_in[1];   // [1, 768] f32
    float* out = (float*)d_out;                    // [32, 768] f32

    attn_fused<<<B * CHUNKS, 256>>>(hidden, querys, out);
}

// round 9
// speedup vs baseline: 1.0028x; 1.0028x over previous
#include <cuda_runtime.h>
#include <math.h>
#include <stdint.h>

// Problem shape (fixed by the reference)
#define B 32
#define S 4096
#define H 768            // 768 floats = 6 float4 per lane across a warp
#define CHUNKS 32        // CTAs per batch
#define WARPS 8          // warps per CTA
#define ROWS_PER_WARP (S / CHUNKS / WARPS)   // 16
#define NPART (B * CHUNKS)                   // 1024 CTA-level partials
#define STAGES 2

// Scratch for CTA partials + per-batch arrival counters (allocation-free).
__device__ float g_pm[NPART];
__device__ float g_pl[NPART];
__device__ float g_pacc[(size_t)NPART * H];   // 3.1 MB
__device__ unsigned int g_count[B] = {};      // reset by last CTA per replay

#define CP_ASYNC16(dst_u32, src_ptr) \
    asm volatile("cp.async.cg.shared.global [%0], [%1], 16;" \
                 :: "r"(dst_u32), "l"(src_ptr))
#define CP_COMMIT() asm volatile("cp.async.commit_group;")
#define CP_WAIT(n)  asm volatile("cp.async.wait_group %0;" :: "n"(n))

// ---------------------------------------------------------------------------
// Fused single-query attention: per-warp cp.async double-buffered row stream,
// online softmax + weighted accumulate, CTA smem merge, last-CTA combine.
// Each lane copies exactly the float4 slots it later reads (i*32+lane), so
// the per-warp pipeline needs no intra-warp synchronization.
// ---------------------------------------------------------------------------
__global__ __launch_bounds__(256, 3)
void attn_fused(const float* __restrict__ hidden, const float* __restrict__ q,
                float* __restrict__ out)
{
    const int bx    = blockIdx.x;            // 0..1023
    const int b     = bx / CHUNKS;           // batch
    const int chunk = bx % CHUNKS;
    const int wid   = threadIdx.x >> 5;
    const int lane  = threadIdx.x & 31;

    // stage buffers: [STAGES][WARPS][192 float4] = 48 KB; later aliased as
    // the 8x768 merge buffer (all async groups drained before reuse)
    __shared__ float4 s_buf[STAGES * WARPS * 192];
    __shared__ float s_m[WARPS];
    __shared__ float s_l[WARPS];
    __shared__ unsigned int s_ticket;

    const float4* qv4 = (const float4*)q;
    float4 qv[6];
#pragma unroll
    for (int i = 0; i < 6; i++) qv[i] = qv4[i * 32 + lane];

    const float* base = hidden + (size_t)b * S * H;
    const int row0 = chunk * (S / CHUNKS) + wid * ROWS_PER_WARP;

    const unsigned sb0 = (unsigned)__cvta_generic_to_shared(s_buf)
                       + (unsigned)((wid * 192 + lane) * 16);
    const unsigned sb1 = sb0 + (unsigned)(WARPS * 192 * 16);

    // issue one row into a stage (6 x 16B per lane), one commit group per row
    #define ISSUE_ROW(r, sb) do {                                        \
        const float* gp_ = base + (size_t)(row0 + (r)) * H + lane * 4;   \
        _Pragma("unroll")                                                \
        for (int i_ = 0; i_ < 6; i_++)                                   \
            CP_ASYNC16((sb) + i_ * 512, gp_ + i_ * 128);                 \
        CP_COMMIT();                                                     \
    } while (0)

    float4 acc[6];
#pragma unroll
    for (int i = 0; i < 6; i++) acc[i] = make_float4(0.f, 0.f, 0.f, 0.f);
    float m = -INFINITY;
    float l = 0.f;

    // consume the row sitting in stage buffer sp_
    #define CONSUME_ROW(sbgen) do {                                      \
        const float4* sp_ = (sbgen);                                     \
        float4 x_[6];                                                    \
        _Pragma("unroll")                                                \
        for (int i_ = 0; i_ < 6; i_++) x_[i_] = sp_[i_ * 32 + lane];     \
        float d_ = 0.f;                                                  \
        _Pragma("unroll")                                                \
        for (int i_ = 0; i_ < 6; i_++) {                                 \
            d_ = fmaf(x_[i_].x, qv[i_].x, d_);                           \
            d_ = fmaf(x_[i_].y, qv[i_].y, d_);                           \
            d_ = fmaf(x_[i_].z, qv[i_].z, d_);                           \
            d_ = fmaf(x_[i_].w, qv[i_].w, d_);                           \
        }                                                                \
        _Pragma("unroll")                                                \
        for (int o_ = 16; o_ > 0; o_ >>= 1)                              \
            d_ += __shfl_xor_sync(0xffffffffu, d_, o_);                  \
        if (d_ > m) {                                                    \
            const float sc_ = __expf(m - d_);                            \
            l *= sc_;                                                    \
            _Pragma("unroll")                                            \
            for (int i_ = 0; i_ < 6; i_++) {                             \
                acc[i_].x *= sc_; acc[i_].y *= sc_;                      \
                acc[i_].z *= sc_; acc[i_].w *= sc_;                      \
            }                                                            \
            m = d_;                                                      \
        }                                                                \
        const float w_ = __expf(d_ - m);                                 \
        l += w_;                                                         \
        _Pragma("unroll")                                                \
        for (int i_ = 0; i_ < 6; i_++) {                                 \
            acc[i_].x = fmaf(w_, x_[i_].x, acc[i_].x);                   \
            acc[i_].y = fmaf(w_, x_[i_].y, acc[i_].y);                   \
            acc[i_].z = fmaf(w_, x_[i_].z, acc[i_].z);                   \
            acc[i_].w = fmaf(w_, x_[i_].w, acc[i_].w);                   \
        }                                                                \
    } while (0)

    const float4* sp0 = s_buf + (wid * 192);
    const float4* sp1 = s_buf + (WARPS * 192 + wid * 192);

    // prologue: fill both stages
    ISSUE_ROW(0, sb0);
    ISSUE_ROW(1, sb1);

    // steady state: rows 0..13 (each issues row r+2 into the freed stage)
#pragma unroll 2
    for (int r = 0; r < ROWS_PER_WARP - 2; r += 2) {
        CP_WAIT(1);
        CONSUME_ROW(sp0);
        ISSUE_ROW(r + 2, sb0);
        CP_WAIT(1);
        CONSUME_ROW(sp1);
        if (r + 3 < ROWS_PER_WARP) ISSUE_ROW(r + 3, sb1);
    }
    // epilogue: rows 14, 15
    CP_WAIT(1);
    CONSUME_ROW(sp0);
    CP_WAIT(0);
    CONSUME_ROW(sp1);

    // ---- CTA-level merge of the 8 warp partials (alias stage memory) ----
    __syncthreads();                        // everyone done streaming
    float* s_acc = (float*)s_buf;           // [WARPS][H] = 24 KB

    if (lane == 0) { s_m[wid] = m; s_l[wid] = l; }
    {
        float4* sa = (float4*)(s_acc + wid * H);
#pragma unroll
        for (int i = 0; i < 6; i++) sa[i * 32 + lane] = acc[i];
    }
    __syncthreads();

    float M = s_m[0];
#pragma unroll
    for (int w = 1; w < WARPS; w++) M = fmaxf(M, s_m[w]);

    float* pa = g_pacc + (size_t)bx * H;
#pragma unroll
    for (int j = 0; j < 3; j++) {
        const int h = threadIdx.x + j * 256;
        float r = 0.f;
#pragma unroll
        for (int w = 0; w < WARPS; w++)
            r = fmaf(__expf(s_m[w] - M), s_acc[w * H + h], r);
        pa[h] = r;
    }
    if (threadIdx.x == 0) {
        float L = 0.f;
#pragma unroll
        for (int w = 0; w < WARPS; w++) L = fmaf(__expf(s_m[w] - M), s_l[w], L);
        g_pm[bx] = M;
        g_pl[bx] = L;
    }

    // ---- last CTA of this batch combines the 32 partials ----
    if (threadIdx.x == 0) {
        __threadfence();                    // partials visible before count
        s_ticket = atomicAdd(&g_count[b], 1u);
    }
    __syncthreads();
    if (s_ticket != CHUNKS - 1) return;

    __threadfence();                        // acquire: see all partials

    const int p0 = b * CHUNKS;
    float GM = -INFINITY;
#pragma unroll
    for (int c = 0; c < CHUNKS; c++) GM = fmaxf(GM, g_pm[p0 + c]);

    float r0 = 0.f, r1 = 0.f, r2 = 0.f, L = 0.f;
    const int h0 = threadIdx.x;
#pragma unroll 4
    for (int c = 0; c < CHUNKS; c++) {
        const float w = __expf(g_pm[p0 + c] - GM);
        const float* pc = g_pacc + (size_t)(p0 + c) * H;
        L  = fmaf(w, g_pl[p0 + c], L);
        r0 = fmaf(w, pc[h0],       r0);
        r1 = fmaf(w, pc[h0 + 256], r1);
        r2 = fmaf(w, pc[h0 + 512], r2);
    }
    const float invL = 1.f / L;
    float* ob = out + b * H;
    ob[h0]       = r0 * invL;
    ob[h0 + 256] = r1 * invL;
    ob[h0 + 512] = r2 * invL;

    if (threadIdx.x == 0) g_count[b] = 0;   // reset for next graph replay
}

extern "C" void kernel_launch(void* const* d_in, const int* in_sizes, int n_in,
                              void* d_out, int out_size)
{
    const float* hidden = (const float*)d_in[0];   // [32, 4096, 768] f32
    const float* querys = (const float*)d_in[1];   // [1, 768] f32
    float* out = (float*)d_out;                    // [32, 768] f32

    attn_fused<<<B * CHUNKS, 256>>>(hidden, querys, out);
}

// round 10
// speedup vs baseline: 1.1849x; 1.1816x over previous
#include <cuda_runtime.h>
#include <math.h>

// Problem shape (fixed by the reference)
#define B 32
#define S 4096
#define H 768            // 768 floats = 6 float4 per lane across a warp
#define CHUNKS 9         // CTAs per batch -> 288 CTAs total (<= 296 slots: 1 wave)
#define WARPS 8          // warps per CTA
#define NPART (B * CHUNKS)                   // 288 CTA-level partials

// Scratch for CTA partials + per-batch arrival counters (allocation-free).
// g_count is statically zero-initialized; the last CTA of each batch resets
// its counter, so every graph replay starts from identical state.
__device__ float g_pm[NPART];
__device__ float g_pl[NPART];
__device__ float g_pacc[(size_t)NPART * H];   // 884 KB (L2-resident)
__device__ unsigned int g_count[B] = {};

// ---------------------------------------------------------------------------
// Fused single-query attention, single wave:
//   - register double-buffered row stream (best measured: ~5.9 TB/s)
//   - online softmax + weighted accumulate, row held in registers
//   - CTA smem merge of 8 warp partials
//   - last CTA per batch combines the 9 partials (overlapped w/ other CTAs)
// ---------------------------------------------------------------------------
__global__ __launch_bounds__(256, 2)
void attn_fused(const float* __restrict__ hidden, const float* __restrict__ q,
                float* __restrict__ out)
{
    const int bx    = blockIdx.x;            // 0..287
    const int b     = bx / CHUNKS;           // batch
    const int chunk = bx % CHUNKS;
    const int wid   = threadIdx.x >> 5;
    const int lane  = threadIdx.x & 31;

    const float4* qv4 = (const float4*)q;
    float4 qv[6];
#pragma unroll
    for (int i = 0; i < 6; i++) qv[i] = qv4[i * 32 + lane];

    const float* base = hidden + (size_t)b * S * H;

    // chunk row range within this batch, then warp sub-range (balanced splits)
    const int c0 = (chunk * S) / CHUNKS;
    const int c1 = ((chunk + 1) * S) / CHUNKS;
    const int w0 = c0 + (wid * (c1 - c0)) / WARPS;
    const int w1 = c0 + ((wid + 1) * (c1 - c0)) / WARPS;
    const int nrows = w1 - w0;               // ~56-57

    float4 acc[6];
#pragma unroll
    for (int i = 0; i < 6; i++) acc[i] = make_float4(0.f, 0.f, 0.f, 0.f);
    float m = -INFINITY;
    float l = 0.f;

    // prefetch first row
    float4 x[6], xn[6];
    {
        const float4* rp = (const float4*)(base + (size_t)w0 * H);
#pragma unroll
        for (int i = 0; i < 6; i++) x[i] = rp[i * 32 + lane];
    }

    for (int r = 0; r < nrows; r++) {
        // prefetch next row (independent of the softmax chain below)
        if (r + 1 < nrows) {
            const float4* rp = (const float4*)(base + (size_t)(w0 + r + 1) * H);
#pragma unroll
            for (int i = 0; i < 6; i++) xn[i] = rp[i * 32 + lane];
        }

        // dot(hidden_row, q)
        float d = 0.f;
#pragma unroll
        for (int i = 0; i < 6; i++) {
            d = fmaf(x[i].x, qv[i].x, d);
            d = fmaf(x[i].y, qv[i].y, d);
            d = fmaf(x[i].z, qv[i].z, d);
            d = fmaf(x[i].w, qv[i].w, d);
        }
#pragma unroll
        for (int o = 16; o > 0; o >>= 1)
            d += __shfl_xor_sync(0xffffffffu, d, o);

        // online softmax update (warp-uniform m, l)
        if (d > m) {
            const float sc = __expf(m - d);   // exp(-inf) = 0 on first row
            l *= sc;
#pragma unroll
            for (int i = 0; i < 6; i++) {
                acc[i].x *= sc; acc[i].y *= sc; acc[i].z *= sc; acc[i].w *= sc;
            }
            m = d;
        }
        const float w = __expf(d - m);
        l += w;
#pragma unroll
        for (int i = 0; i < 6; i++) {
            acc[i].x = fmaf(w, x[i].x, acc[i].x);
            acc[i].y = fmaf(w, x[i].y, acc[i].y);
            acc[i].z = fmaf(w, x[i].z, acc[i].z);
            acc[i].w = fmaf(w, x[i].w, acc[i].w);
        }

#pragma unroll
        for (int i = 0; i < 6; i++) x[i] = xn[i];
    }

    // ---- CTA-level merge of the 8 warp partials through shared memory ----
    __shared__ float s_m[WARPS];
    __shared__ float s_l[WARPS];
    __shared__ float s_acc[WARPS][H];        // 24 KB
    __shared__ unsigned int s_ticket;

    if (lane == 0) { s_m[wid] = m; s_l[wid] = l; }
    {
        float4* sa = (float4*)s_acc[wid];
#pragma unroll
        for (int i = 0; i < 6; i++) sa[i * 32 + lane] = acc[i];
    }
    __syncthreads();

    float M = s_m[0];
#pragma unroll
    for (int w = 1; w < WARPS; w++) M = fmaxf(M, s_m[w]);

    // each thread owns 3 h-values (768 / 256): conflict-free LDS, coalesced STG
    float* pa = g_pacc + (size_t)bx * H;
#pragma unroll
    for (int j = 0; j < 3; j++) {
        const int h = threadIdx.x + j * 256;
        float r = 0.f;
#pragma unroll
        for (int w = 0; w < WARPS; w++)
            r = fmaf(__expf(s_m[w] - M), s_acc[w][h], r);
        pa[h] = r;
    }
    if (threadIdx.x == 0) {
        float L = 0.f;
#pragma unroll
        for (int w = 0; w < WARPS; w++) L = fmaf(__expf(s_m[w] - M), s_l[w], L);
        g_pm[bx] = M;
        g_pl[bx] = L;
    }

    // ---- last CTA of this batch combines the 9 partials ----
    if (threadIdx.x == 0) {
        __threadfence();                      // partials visible before count
        s_ticket = atomicAdd(&g_count[b], 1u);
    }
    __syncthreads();
    if (s_ticket != CHUNKS - 1) return;

    __threadfence();                          // acquire: see all partials

    const int p0 = b * CHUNKS;
    float GM = -INFINITY;
#pragma unroll
    for (int c = 0; c < CHUNKS; c++) GM = fmaxf(GM, g_pm[p0 + c]);

    float r0 = 0.f, r1 = 0.f, r2 = 0.f, L = 0.f;
    const int h0 = threadIdx.x;
#pragma unroll
    for (int c = 0; c < CHUNKS; c++) {
        const float w = __expf(g_pm[p0 + c] - GM);
        const float* pc = g_pacc + (size_t)(p0 + c) * H;
        L  = fmaf(w, g_pl[p0 + c], L);
        r0 = fmaf(w, pc[h0],       r0);
        r1 = fmaf(w, pc[h0 + 256], r1);
        r2 = fmaf(w, pc[h0 + 512], r2);
    }
    const float invL = 1.f / L;
    float* ob = out + b * H;
    ob[h0]       = r0 * invL;
    ob[h0 + 256] = r1 * invL;
    ob[h0 + 512] = r2 * invL;

    if (threadIdx.x == 0) g_count[b] = 0;     // reset for next graph replay
}

extern "C" void kernel_launch(void* const* d_in, const int* in_sizes, int n_in,
                              void* d_out, int out_size)
{
    const float* hidden = (const float*)d_in[0];   // [32, 4096, 768] f32
    const float* querys = (const float*)d_in[1];   // [1, 768] f32
    float* out = (float*)d_out;                    // [32, 768] f32

    attn_fused<<<B * CHUNKS, 256>>>(hidden, querys, out);
}